// round 10
// baseline (speedup 1.0000x reference)
#include <cuda_runtime.h>
#include <stdint.h>

// EmotionModel: out = r + clip(softmax(r * (e @ (W_Q^T W_K)))^3 * colsum(W_D) + sum(b_D), -1, 1)
// B = 1,048,576 rows, D = 7.
// R10: R9 = 20.4us; nothing saturated (DRAM 38%, L1 55%, issue 51%), occ 44.7%
// reg-limited (64 regs -> 4 CTAs/SM). Latency-bound => raise occupancy:
// __launch_bounds__(256,5) (51-reg cap), col[] moved to smem reads, p reuses raw.

#define THREADS 256
#define RPT 2                              // rows per thread
#define ROWS_PER_BLOCK (THREADS * RPT)     // 512
#define D 7
#define FLOATS_PER_BLOCK (ROWS_PER_BLOCK * D)   // 3584
#define N4 (FLOATS_PER_BLOCK / 4)               // 896 float4s

// e^x on the FMA pipe (no MUFU). Valid for x <= 0 (softmax shifted args).
__device__ __forceinline__ float fexp(float x) {
    const float L2E = 1.442695041f;
    float z = fmaf(x, L2E, 12582912.0f);       // 1.5*2^23 magic round
    int   i = __float_as_int(z);               // low mantissa bits hold n (+bias)
    float n = z - 12582912.0f;
    float f = fmaf(x, L2E, -n);                // f in [-0.5, 0.5]
    float p =             1.3333558146e-3f;
    p = fmaf(p, f,        9.6181291076e-3f);
    p = fmaf(p, f,        5.5504108664e-2f);
    p = fmaf(p, f,        2.4022650695e-1f);
    p = fmaf(p, f,        6.9314718056e-1f);
    p = fmaf(p, f,        1.0f);
    return __int_as_float(__float_as_int(p) + (i << 23));
}

template <bool VEC4>
__global__ __launch_bounds__(THREADS, 5)
void emotion_kernel(const float* __restrict__ rep,
                    const float* __restrict__ emo,
                    const float* __restrict__ WQ,
                    const float* __restrict__ WK,
                    const float* __restrict__ WD,
                    const float* __restrict__ bD,
                    float* __restrict__ out)
{
    __shared__ __align__(16) float sE[FLOATS_PER_BLOCK];   // 14 KB staging (reused for output)
    __shared__ __align__(16) float sR[FLOATS_PER_BLOCK];   // 14 KB staging
    __shared__ float sWQ[49];
    __shared__ float sWK[49];
    __shared__ float sM[49];       // M[k][i] = sum_j WQ[j][k] * WK[j][i]
    __shared__ float sCol[D];      // colsum(W_D)
    __shared__ float sSumB;        // sum(b_D)

    const int tid = threadIdx.x;

    // ---- tiny per-block precompute -------------------------------------
    if (tid < 49) { sWQ[tid] = WQ[tid]; sWK[tid] = WK[tid]; }
    __syncthreads();
    if (tid < 49) {
        const int k = tid / 7, i = tid % 7;
        float acc = 0.f;
        #pragma unroll
        for (int j = 0; j < 7; j++) acc = fmaf(sWQ[j * 7 + k], sWK[j * 7 + i], acc);
        sM[tid] = acc;
    }
    if (tid >= 64 && tid < 64 + D) {
        const int i = tid - 64;
        float c = 0.f;
        #pragma unroll
        for (int j = 0; j < 7; j++) c += WD[j * 7 + i];
        sCol[i] = c;
    }
    if (tid == 96) {
        float s = 0.f;
        #pragma unroll
        for (int j = 0; j < 7; j++) s += bD[j];
        sSumB = s;
    }

    // ---- coalesced staging of both inputs ------------------------------
    const size_t base = (size_t)blockIdx.x * FLOATS_PER_BLOCK;   // 14336B per block
    if (VEC4) {
        const float4* __restrict__ e4 = (const float4*)(emo + base);
        const float4* __restrict__ r4 = (const float4*)(rep + base);
        float4* se4 = (float4*)sE;
        float4* sr4 = (float4*)sR;
        #pragma unroll
        for (int i = tid; i < N4; i += THREADS) {
            se4[i] = e4[i];
            sr4[i] = r4[i];
        }
    } else {
        const float* __restrict__ ep = emo + base;
        const float* __restrict__ rp = rep + base;
        #pragma unroll 4
        for (int i = tid; i < FLOATS_PER_BLOCK; i += THREADS) {
            sE[i] = ep[i];
            sR[i] = rp[i];
        }
    }
    __syncthreads();   // covers sM/sCol/sSumB writes and staging stores

    const float sumb = sSumB;

    // ---- per-row math (smem row access is bank-conflict-free: 7*tid mod 32) ----
    #pragma unroll
    for (int r = 0; r < RPT; r++) {
        const int row = tid + r * THREADS;
        float e[D], rv[D];
        #pragma unroll
        for (int i = 0; i < D; i++) { e[i] = sE[row * D + i]; rv[i] = sR[row * D + i]; }

        float raw[D];
        #pragma unroll
        for (int i = 0; i < D; i++) {
            float acc = 0.f;
            #pragma unroll
            for (int k = 0; k < D; k++) acc = fmaf(e[k], sM[k * 7 + i], acc);  // broadcast LDS
            raw[i] = acc * rv[i];
        }

        // softmax over 7 (exp on the FMA pipe, not MUFU); p overwrites raw
        float mx = raw[0];
        #pragma unroll
        for (int i = 1; i < D; i++) mx = fmaxf(mx, raw[i]);
        float psum = 0.f;
        #pragma unroll
        for (int i = 0; i < D; i++) { raw[i] = fexp(raw[i] - mx); psum += raw[i]; }
        const float inv = __fdividef(1.0f, psum);

        #pragma unroll
        for (int i = 0; i < D; i++) {
            const float s  = raw[i] * inv;
            const float s3 = s * s * s;
            const float d  = fminf(fmaxf(fmaf(s3, sCol[i], sumb), -1.0f), 1.0f);
            sE[row * D + i] = rv[i] + d;   // reuse e-staging buffer for output
        }
    }
    __syncthreads();

    // ---- coalesced store -----------------------------------------------
    if (VEC4) {
        float4* o4 = (float4*)(out + base);
        const float4* se4 = (const float4*)sE;
        #pragma unroll
        for (int i = tid; i < N4; i += THREADS) o4[i] = se4[i];
    } else {
        float* __restrict__ op = out + base;
        #pragma unroll 4
        for (int i = tid; i < FLOATS_PER_BLOCK; i += THREADS) op[i] = sE[i];
    }
}

extern "C" void kernel_launch(void* const* d_in, const int* in_sizes, int n_in,
                              void* d_out, int out_size)
{
    const float* rep = (const float*)d_in[0];
    const float* emo = (const float*)d_in[1];
    const float* WQ  = (const float*)d_in[2];
    const float* WK  = (const float*)d_in[3];
    const float* WD  = (const float*)d_in[4];
    const float* bD  = (const float*)d_in[5];
    float* out = (float*)d_out;

    const int n_rows = in_sizes[0] / D;                               // 1,048,576
    const int grid = (n_rows + ROWS_PER_BLOCK - 1) / ROWS_PER_BLOCK;  // 2048 exact

    const bool aligned16 =
        ((((uintptr_t)rep) | ((uintptr_t)emo) | ((uintptr_t)out)) & 15u) == 0;

    if (aligned16)
        emotion_kernel<true><<<grid, THREADS>>>(rep, emo, WQ, WK, WD, bD, out);
    else
        emotion_kernel<false><<<grid, THREADS>>>(rep, emo, WQ, WK, WD, bD, out);
}

// round 13
// speedup vs baseline: 1.0957x; 1.0957x over previous
#include <cuda_runtime.h>
#include <stdint.h>

// EmotionModel: out = r + clip(softmax(r * (e @ (W_Q^T W_K)))^3 * colsum(W_D) + sum(b_D), -1, 1)
// B = 1,048,576 rows, D = 7.
// R13: same cp.async double-buffer pipeline as R11/R12 but STATIC smem
// (TILE_ROWS=256, 4 x 7168B = 28KB) -> no cudaFuncSetAttribute in
// kernel_launch (removes any "device limits changed" guard risk under graph
// capture). 1024 CTAs x 4 tiles; load(t+1) overlaps compute+store(t).

#define THREADS 256
#define TILE_ROWS 256
#define D 7
#define TILE_FLOATS (TILE_ROWS * D)        // 1792 floats = 7168 B per buffer
#define NT4 (TILE_FLOATS / 4)              // 448 float4 per buffer per tile
#define GRID 1024

// smem float offsets: [E buf0][E buf1][R buf0][R buf1]
#define E_OFF(b) ((b) * TILE_FLOATS)
#define R_OFF(b) (2 * TILE_FLOATS + (b) * TILE_FLOATS)

__device__ __forceinline__ void cp16(uint32_t dst, const void* src) {
    asm volatile("cp.async.cg.shared.global [%0], [%1], 16;" :: "r"(dst), "l"(src));
}
__device__ __forceinline__ void cp4(uint32_t dst, const void* src) {
    asm volatile("cp.async.ca.shared.global [%0], [%1], 4;" :: "r"(dst), "l"(src));
}
#define CP_COMMIT()  asm volatile("cp.async.commit_group;")
#define CP_WAIT(N)   asm volatile("cp.async.wait_group %0;" :: "n"(N))

// e^x on the FMA pipe (no MUFU). Valid for x <= 0 (softmax shifted args).
__device__ __forceinline__ float fexp(float x) {
    const float L2E = 1.442695041f;
    float z = fmaf(x, L2E, 12582912.0f);       // 1.5*2^23 magic round
    int   i = __float_as_int(z);
    float n = z - 12582912.0f;
    float f = fmaf(x, L2E, -n);                // f in [-0.5, 0.5]
    float p =             1.3333558146e-3f;
    p = fmaf(p, f,        9.6181291076e-3f);
    p = fmaf(p, f,        5.5504108664e-2f);
    p = fmaf(p, f,        2.4022650695e-1f);
    p = fmaf(p, f,        6.9314718056e-1f);
    p = fmaf(p, f,        1.0f);
    return __int_as_float(__float_as_int(p) + (i << 23));
}

template <bool VEC4>
__global__ __launch_bounds__(THREADS)
void emotion_kernel(const float* __restrict__ rep,
                    const float* __restrict__ emo,
                    const float* __restrict__ WQ,
                    const float* __restrict__ WK,
                    const float* __restrict__ WD,
                    const float* __restrict__ bD,
                    float* __restrict__ out,
                    int ntiles)
{
    __shared__ __align__(16) float dsm[4 * TILE_FLOATS];   // 28 KB, static
    __shared__ float sWQ[49];
    __shared__ float sWK[49];
    __shared__ float sM[49];       // M[k][i] = sum_j WQ[j][k] * WK[j][i]
    __shared__ float sCol[D];      // colsum(W_D)
    __shared__ float sSumB;        // sum(b_D)

    const int tid = threadIdx.x;
    const uint32_t dsm_base = (uint32_t)__cvta_generic_to_shared(dsm);

    // ---- tiny per-block precompute --------------------------------------
    if (tid < 49) { sWQ[tid] = WQ[tid]; sWK[tid] = WK[tid]; }
    __syncthreads();
    if (tid < 49) {
        const int k = tid / 7, i = tid % 7;
        float acc = 0.f;
        #pragma unroll
        for (int j = 0; j < 7; j++) acc = fmaf(sWQ[j * 7 + k], sWK[j * 7 + i], acc);
        sM[tid] = acc;
    }
    if (tid >= 64 && tid < 64 + D) {
        const int i = tid - 64;
        float c = 0.f;
        #pragma unroll
        for (int j = 0; j < 7; j++) c += WD[j * 7 + i];
        sCol[i] = c;
    }
    if (tid == 96) {
        float s = 0.f;
        #pragma unroll
        for (int j = 0; j < 7; j++) s += bD[j];
        sSumB = s;
    }

    // issue async load of a tile into buffer b
    auto issue_load = [&](int tile_, int b) {
        const size_t base = (size_t)tile_ * TILE_FLOATS;
        if (VEC4) {
            const float4* e4 = (const float4*)(emo + base);
            const float4* r4 = (const float4*)(rep + base);
            const uint32_t de = dsm_base + E_OFF(b) * 4;
            const uint32_t dr = dsm_base + R_OFF(b) * 4;
            for (int i = tid; i < NT4; i += THREADS) {
                cp16(de + i * 16, e4 + i);
                cp16(dr + i * 16, r4 + i);
            }
        } else {
            const float* ep = emo + base;
            const float* rp = rep + base;
            const uint32_t de = dsm_base + E_OFF(b) * 4;
            const uint32_t dr = dsm_base + R_OFF(b) * 4;
            for (int i = tid; i < TILE_FLOATS; i += THREADS) {
                cp4(de + i * 4, ep + i);
                cp4(dr + i * 4, rp + i);
            }
        }
    };

    int tile = blockIdx.x;
    if (tile < ntiles) { issue_load(tile, 0); }
    CP_COMMIT();

    int p = 0;  // current buffer parity
    while (tile < ntiles) {
        const int next = tile + GRID;
        const bool has_next = next < ntiles;
        if (has_next) {
            issue_load(next, p ^ 1);
            CP_COMMIT();
            CP_WAIT(1);           // current tile's group complete
        } else {
            CP_WAIT(0);
        }
        __syncthreads();          // data visible to all; also covers sM/sCol init

        float* bufE = dsm + E_OFF(p);
        float* bufR = dsm + R_OFF(p);
        const float sumb = sSumB;

        // ---- per-row math: one row per thread (7*tid mod 32 conflict-free)
        {
            const int row = tid;
            float e[D], rv[D];
            #pragma unroll
            for (int i = 0; i < D; i++) { e[i] = bufE[row * D + i]; rv[i] = bufR[row * D + i]; }

            float raw[D];
            #pragma unroll
            for (int i = 0; i < D; i++) {
                float acc = 0.f;
                #pragma unroll
                for (int k = 0; k < D; k++) acc = fmaf(e[k], sM[k * 7 + i], acc);
                raw[i] = acc * rv[i];
            }

            float mx = raw[0];
            #pragma unroll
            for (int i = 1; i < D; i++) mx = fmaxf(mx, raw[i]);
            float psum = 0.f;
            #pragma unroll
            for (int i = 0; i < D; i++) { raw[i] = fexp(raw[i] - mx); psum += raw[i]; }
            const float inv = __fdividef(1.0f, psum);

            #pragma unroll
            for (int i = 0; i < D; i++) {
                const float s  = raw[i] * inv;
                const float s3 = s * s * s;
                const float d  = fminf(fmaxf(fmaf(s3, sCol[i], sumb), -1.0f), 1.0f);
                bufE[row * D + i] = rv[i] + d;   // overwrite E buffer with output
            }
        }
        __syncthreads();          // outputs complete in smem

        // ---- coalesced store of tile ------------------------------------
        const size_t base = (size_t)tile * TILE_FLOATS;
        if (VEC4) {
            float4* o4 = (float4*)(out + base);
            const float4* se4 = (const float4*)bufE;
            for (int i = tid; i < NT4; i += THREADS) o4[i] = se4[i];
        } else {
            float* op = out + base;
            for (int i = tid; i < TILE_FLOATS; i += THREADS) op[i] = bufE[i];
        }

        if (!has_next) break;
        __syncthreads();          // buffer p fully read before tile+2 load reuses it
        tile = next;
        p ^= 1;
    }
}

extern "C" void kernel_launch(void* const* d_in, const int* in_sizes, int n_in,
                              void* d_out, int out_size)
{
    const float* rep = (const float*)d_in[0];
    const float* emo = (const float*)d_in[1];
    const float* WQ  = (const float*)d_in[2];
    const float* WK  = (const float*)d_in[3];
    const float* WD  = (const float*)d_in[4];
    const float* bD  = (const float*)d_in[5];
    float* out = (float*)d_out;

    const int n_rows = in_sizes[0] / D;                        // 1,048,576
    const int ntiles = (n_rows + TILE_ROWS - 1) / TILE_ROWS;   // 4096 exact

    const bool aligned16 =
        ((((uintptr_t)rep) | ((uintptr_t)emo) | ((uintptr_t)out)) & 15u) == 0;

    if (aligned16)
        emotion_kernel<true><<<GRID, THREADS>>>(rep, emo, WQ, WK, WD, bD, out, ntiles);
    else
        emotion_kernel<false><<<GRID, THREADS>>>(rep, emo, WQ, WK, WD, bD, out, ntiles);
}